// round 15
// baseline (speedup 1.0000x reference)
#include <cuda_runtime.h>
#include <cuda_fp16.h>
#include <cstdint>
#include <math.h>

#define NEXP 16
#define TOPK 4
#define HDIM 2048
#define IDIM 2048
#define TMAX 4096
#define ALPHA 1.702f
#define LIMIT 7.0f
#define NKB 32     // 2048 / 64
#define KHALF 64   // k-halfs per stage
#define LDK 144    // A row pitch bytes

__device__ int    g_cnt[NEXP];
__device__ int    g_tok[NEXP * TMAX];
__device__ int    g_tslot[TMAX * TOPK];
__device__ float  g_twt[TMAX * TOPK];
__device__ __half g_xh[(size_t)TMAX * HDIM];
__device__ __half g_w1h[(size_t)NEXP * HDIM * 4096];   // fp16 w1, native [k][n]
__device__ __half g_w2h[(size_t)NEXP * IDIM * HDIM];   // fp16 w2, native [k][n]
__device__ __half g_acth[(size_t)NEXP * TMAX * IDIM];
__device__ __half g_parth[(size_t)NEXP * TMAX * HDIM]; // fp16 partials

// ---------------- helpers ----------------
__device__ __forceinline__ void cp16(const void* smem_dst, const void* gsrc, bool pred) {
  uint32_t d = (uint32_t)__cvta_generic_to_shared(smem_dst);
  int sz = pred ? 16 : 0;
  asm volatile("cp.async.cg.shared.global [%0], [%1], 16, %2;" :: "r"(d), "l"(gsrc), "r"(sz));
}
__device__ __forceinline__ void cp_commit() { asm volatile("cp.async.commit_group;"); }

__device__ __forceinline__ void mma16(float* c, const uint32_t* a, const uint32_t* b) {
  asm volatile(
      "mma.sync.aligned.m16n8k16.row.col.f32.f16.f16.f32 "
      "{%0,%1,%2,%3}, {%4,%5,%6,%7}, {%8,%9}, {%0,%1,%2,%3};"
      : "+f"(c[0]), "+f"(c[1]), "+f"(c[2]), "+f"(c[3])
      : "r"(a[0]), "r"(a[1]), "r"(a[2]), "r"(a[3]), "r"(b[0]), "r"(b[1]));
}
__device__ __forceinline__ uint32_t lds32(const char* smem, uint32_t off) {
  return *(const uint32_t*)(smem + off);
}
__device__ __forceinline__ void ldmx4t(uint32_t& r0, uint32_t& r1, uint32_t& r2, uint32_t& r3,
                                       uint32_t addr) {
  asm volatile("ldmatrix.sync.aligned.m8n8.x4.trans.shared.b16 {%0,%1,%2,%3}, [%4];"
               : "=r"(r0), "=r"(r1), "=r"(r2), "=r"(r3) : "r"(addr));
}

// ---------------- router ----------------
__global__ __launch_bounds__(256) void router_kernel(const float* __restrict__ x,
                                                     const float* __restrict__ rw,
                                                     const float* __restrict__ rb) {
  int warp = threadIdx.x >> 5, lane = threadIdx.x & 31;
  int t = blockIdx.x * 8 + warp;
  float acc[NEXP];
#pragma unroll
  for (int e = 0; e < NEXP; e++) acc[e] = 0.f;
  const float* xr = x + (size_t)t * HDIM;
  for (int h = lane; h < HDIM; h += 32) {
    float xv = xr[h];
#pragma unroll
    for (int e = 0; e < NEXP; e++) acc[e] = fmaf(xv, rw[e * HDIM + h], acc[e]);
  }
#pragma unroll
  for (int e = 0; e < NEXP; e++)
#pragma unroll
    for (int o = 16; o > 0; o >>= 1) acc[e] += __shfl_xor_sync(0xffffffffu, acc[e], o);
  if (lane == 0) {
    float v[NEXP];
#pragma unroll
    for (int e = 0; e < NEXP; e++) v[e] = acc[e] + rb[e];
    int ids[TOPK]; float vals[TOPK];
#pragma unroll
    for (int j = 0; j < TOPK; j++) {
      float best = -1e30f; int bi = 0;
#pragma unroll
      for (int e = 0; e < NEXP; e++)
        if (v[e] > best) { best = v[e]; bi = e; }
      ids[j] = bi; vals[j] = best; v[bi] = -1e30f;
    }
    float m = vals[0], s = 0.f, w[TOPK];
#pragma unroll
    for (int j = 0; j < TOPK; j++) { w[j] = expf(vals[j] - m); s += w[j]; }
    float inv = 1.f / s;
#pragma unroll
    for (int j = 0; j < TOPK; j++) {
      int e = ids[j];
      int p = atomicAdd(&g_cnt[e], 1);
      g_tok[e * TMAX + p] = t;
      g_tslot[t * TOPK + j] = e * TMAX + p;
      g_twt[t * TOPK + j] = w[j] * inv;
    }
  }
}

// ---------------- prep: fp16 conversions ----------------
__global__ __launch_bounds__(256) void cvt_kernel(const float* __restrict__ src,
                                                  __half* __restrict__ dst) {
  size_t i = ((size_t)blockIdx.x * 256 + threadIdx.x);
  float4 v = ((const float4*)src)[i];
  __half2 h0 = __floats2half2_rn(v.x, v.y);
  __half2 h1 = __floats2half2_rn(v.z, v.w);
  uint2 o = { *(uint32_t*)&h0, *(uint32_t*)&h1 };
  ((uint2*)dst)[i] = o;
}

// ---------------- GEMM1: X @ w1 (gate|up) -> clipped GLU -> g_acth ----------------
// CTA tile: 128m x (64 gate + 64 up). 256 threads, 2 CTAs/SM.
// stage s at s*34816: A [128 x LDK] at +0, B [64 k-rows x 256B] at +18432
// per k-row: chunks j=0..7 gate cols n0+j*8, j=8..15 up cols 2048+n0+(j-8)*8
#define STG1 34816
#define SMEM1 (2 * STG1 + 512)

__global__ __launch_bounds__(256, 2) void gemm1_kernel(const float* __restrict__ b1) {
  int e = blockIdx.z;
  int cnt = g_cnt[e];
  int m0 = blockIdx.x * 128;
  if (m0 >= cnt) return;
  int n0 = blockIdx.y * 64;

  extern __shared__ __align__(16) char smem[];
  uint32_t sbase = (uint32_t)__cvta_generic_to_shared(smem);
  int* toks = (int*)(smem + 2 * STG1);
  int tid = threadIdx.x, w = tid >> 5, lane = tid & 31;
  int g = lane >> 2, tq = lane & 3;

  if (tid < 128) toks[tid] = (m0 + tid < cnt) ? g_tok[e * TMAX + m0 + tid] : -1;
  __syncthreads();

  // A: 1024 chunks, 4 per thread
  const __half* asrc[4]; uint32_t adst[4]; bool apred[4];
#pragma unroll
  for (int q = 0; q < 4; q++) {
    int idx = tid + q * 256;
    int row = idx >> 3, ch = idx & 7;
    int tok = toks[row];
    apred[q] = tok >= 0;
    asrc[q] = g_xh + (size_t)(tok < 0 ? 0 : tok) * HDIM + ch * 8;
    adst[q] = row * LDK + ch * 16;
  }

  // B: 1024 chunks (64 rows x 16), 4 per thread
  const __half* w1e = g_w1h + (size_t)e * HDIM * 4096;
  const __half* bsrc[4]; uint32_t bdst[4];
#pragma unroll
  for (int q = 0; q < 4; q++) {
    int C = tid + q * 256;
    int k = C >> 4, j = C & 15;
    int col = (j < 8) ? (n0 + j * 8) : (2048 + n0 + (j - 8) * 8);
    bsrc[q] = w1e + (size_t)k * 4096 + col;
    bdst[q] = 18432 + k * 256 + ((j ^ (k & 7)) << 4);
  }

  auto ld = [&](int kb) {
    char* base = smem + (kb & 1) * STG1;
    size_t ako = (size_t)kb * KHALF;
#pragma unroll
    for (int q = 0; q < 4; q++) cp16(base + adst[q], asrc[q] + ako, apred[q]);
    size_t bko = (size_t)kb * KHALF * 4096;
#pragma unroll
    for (int q = 0; q < 4; q++) cp16(base + bdst[q], bsrc[q] + bko, true);
    cp_commit();
  };

  float cg[2][4][4], cu[2][4][4];
#pragma unroll
  for (int mi = 0; mi < 2; mi++)
#pragma unroll
    for (int ni = 0; ni < 4; ni++)
#pragma unroll
      for (int q = 0; q < 4; q++) { cg[mi][ni][q] = 0.f; cu[mi][ni][q] = 0.f; }

  int wm = (w & 3) * 32, wn = (w >> 2) * 32;   // 4 m-groups x 2 n-groups
  int lr = lane & 7, lci = lane >> 4;
  uint32_t krow = ((lane >> 3) & 1) * 8 + lr;
  uint32_t k7 = krow & 7;
  uint32_t browoff = krow * 256;
  uint32_t cgb = wn >> 3;          // gate chunks cgb..cgb+3
  uint32_t cub = 8 + (wn >> 3);    // up chunks

  ld(0);

  for (int kb = 0; kb < NKB; kb++) {
    asm volatile("cp.async.wait_group 0;");
    __syncthreads();
    if (kb + 1 < NKB) ld(kb + 1);
    const char* Ab = smem + (kb & 1) * STG1;
    uint32_t Bu = sbase + (kb & 1) * STG1 + 18432;
#pragma unroll
    for (int kk = 0; kk < 4; kk++) {
      uint32_t a[2][4];
#pragma unroll
      for (int mi = 0; mi < 2; mi++) {
        uint32_t base = (wm + mi * 16 + g) * LDK + kk * 32 + tq * 4;
        a[mi][0] = lds32(Ab, base);
        a[mi][1] = lds32(Ab, base + 8 * LDK);
        a[mi][2] = lds32(Ab, base + 16);
        a[mi][3] = lds32(Ab, base + 8 * LDK + 16);
      }
      uint32_t bg[4][2], bu[4][2];
      uint32_t kkoff = Bu + kk * 4096 + browoff;
#pragma unroll
      for (int p = 0; p < 2; p++) {
        uint32_t c0 = cgb + 2 * p + lci;
        ldmx4t(bg[2 * p][0], bg[2 * p][1], bg[2 * p + 1][0], bg[2 * p + 1][1],
               kkoff + ((c0 ^ k7) << 4));
        uint32_t c1 = cub + 2 * p + lci;
        ldmx4t(bu[2 * p][0], bu[2 * p][1], bu[2 * p + 1][0], bu[2 * p + 1][1],
               kkoff + ((c1 ^ k7) << 4));
      }
#pragma unroll
      for (int ni = 0; ni < 4; ni++)
#pragma unroll
        for (int mi = 0; mi < 2; mi++) {
          mma16(cg[mi][ni], a[mi], bg[ni]);
          mma16(cu[mi][ni], a[mi], bu[ni]);
        }
    }
  }

  const float* b1e = b1 + (size_t)e * 4096;
#pragma unroll
  for (int ni = 0; ni < 4; ni++) {
    int col = n0 + wn + ni * 8 + 2 * tq;
    float bg0 = b1e[col], bg1 = b1e[col + 1];
    float bu0 = b1e[2048 + col], bu1 = b1e[2048 + col + 1];
#pragma unroll
    for (int mi = 0; mi < 2; mi++) {
#pragma unroll
      for (int rr = 0; rr < 2; rr++) {
        int rl = wm + mi * 16 + rr * 8 + g;
        if (m0 + rl >= cnt) continue;
        float gv0 = cg[mi][ni][rr * 2 + 0] + bg0;
        float gv1 = cg[mi][ni][rr * 2 + 1] + bg1;
        float uv0 = cu[mi][ni][rr * 2 + 0] + bu0;
        float uv1 = cu[mi][ni][rr * 2 + 1] + bu1;
        gv0 = fminf(gv0, LIMIT); gv1 = fminf(gv1, LIMIT);
        uv0 = fminf(fmaxf(uv0, -LIMIT), LIMIT);
        uv1 = fminf(fmaxf(uv1, -LIMIT), LIMIT);
        float a0 = (uv0 + 1.f) * gv0 / (1.f + __expf(-ALPHA * gv0));
        float a1 = (uv1 + 1.f) * gv1 / (1.f + __expf(-ALPHA * gv1));
        __half2 h = __floats2half2_rn(a0, a1);
        *(__half2*)(g_acth + ((size_t)e * TMAX + m0 + rl) * 2048 + col) = h;
      }
    }
  }
}

// ---------------- GEMM2: acts @ w2 -> g_parth (fp16 partials) ----------------
// stage s at s*34816: A [128 x LDK] at +0, B [64 k-rows x 256B] at +18432
#define STG2 34816
#define SMEM2 (2 * STG2)

__global__ __launch_bounds__(256, 2) void gemm2_kernel() {
  int e = blockIdx.z;
  int cnt = g_cnt[e];
  int m0 = blockIdx.x * 128;
  if (m0 >= cnt) return;
  int n0 = blockIdx.y * 128;

  extern __shared__ __align__(16) char smem[];
  uint32_t sbase = (uint32_t)__cvta_generic_to_shared(smem);
  int tid = threadIdx.x, w = tid >> 5, lane = tid & 31;
  int g = lane >> 2, tq = lane & 3;

  const __half* acte = g_acth + (size_t)e * TMAX * 2048;
  const __half* w2h = g_w2h + (size_t)e * IDIM * HDIM;

  // A: 1024 chunks, 4 per thread
  const __half* asrc[4]; uint32_t adst[4]; bool apred[4];
#pragma unroll
  for (int q = 0; q < 4; q++) {
    int idx = tid + q * 256;
    int row = idx >> 3, ch = idx & 7;
    apred[q] = (m0 + row) < cnt;
    asrc[q] = acte + (size_t)(m0 + row) * 2048 + ch * 8;
    adst[q] = row * LDK + ch * 16;
  }
  // B: 1024 chunks, 4 per thread
  const __half* bsrc[4]; uint32_t bdst[4];
#pragma unroll
  for (int q = 0; q < 4; q++) {
    int C = tid + q * 256;
    int k = C >> 4, j = C & 15;
    bsrc[q] = w2h + (size_t)k * 2048 + n0 + j * 8;
    bdst[q] = 18432 + k * 256 + ((j ^ (k & 7)) << 4);
  }

  auto ld = [&](int kb) {
    char* base = smem + (kb & 1) * STG2;
    size_t ako = (size_t)kb * KHALF;
#pragma unroll
    for (int q = 0; q < 4; q++) cp16(base + adst[q], asrc[q] + ako, apred[q]);
    size_t bko = (size_t)kb * KHALF * 2048;
#pragma unroll
    for (int q = 0; q < 4; q++) cp16(base + bdst[q], bsrc[q] + bko, true);
    cp_commit();
  };

  float cc[2][8][4];
#pragma unroll
  for (int mi = 0; mi < 2; mi++)
#pragma unroll
    for (int ni = 0; ni < 8; ni++)
#pragma unroll
      for (int q = 0; q < 4; q++) cc[mi][ni][q] = 0.f;

  int wm = (w & 3) * 32, wn = (w >> 2) * 64;
  int lr = lane & 7, lci = lane >> 4;
  uint32_t krow = ((lane >> 3) & 1) * 8 + lr;
  uint32_t k7 = krow & 7;
  uint32_t browoff = krow * 256;
  uint32_t cb = wn >> 3;

  ld(0);

  for (int kb = 0; kb < NKB; kb++) {
    asm volatile("cp.async.wait_group 0;");
    __syncthreads();
    if (kb + 1 < NKB) ld(kb + 1);
    const char* Ab = smem + (kb & 1) * STG2;
    uint32_t Bu = sbase + (kb & 1) * STG2 + 18432;
#pragma unroll
    for (int kk = 0; kk < 4; kk++) {
      uint32_t a[2][4];
#pragma unroll
      for (int mi = 0; mi < 2; mi++) {
        uint32_t base = (wm + mi * 16 + g) * LDK + kk * 32 + tq * 4;
        a[mi][0] = lds32(Ab, base);
        a[mi][1] = lds32(Ab, base + 8 * LDK);
        a[mi][2] = lds32(Ab, base + 16);
        a[mi][3] = lds32(Ab, base + 8 * LDK + 16);
      }
      uint32_t b[8][2];
      uint32_t kkoff = Bu + kk * 4096 + browoff;
#pragma unroll
      for (int p = 0; p < 4; p++) {
        uint32_t c0 = cb + 2 * p + lci;
        ldmx4t(b[2 * p][0], b[2 * p][1], b[2 * p + 1][0], b[2 * p + 1][1],
               kkoff + ((c0 ^ k7) << 4));
      }
#pragma unroll
      for (int ni = 0; ni < 8; ni++)
#pragma unroll
        for (int mi = 0; mi < 2; mi++) mma16(cc[mi][ni], a[mi], b[ni]);
    }
  }

  __half* parte = g_parth + (size_t)e * TMAX * 2048;
#pragma unroll
  for (int mi = 0; mi < 2; mi++) {
#pragma unroll
    for (int rr = 0; rr < 2; rr++) {
      int rl = wm + mi * 16 + rr * 8 + g;
      if (m0 + rl >= cnt) continue;
      __half* prow = parte + (size_t)(m0 + rl) * 2048 + n0;
#pragma unroll
      for (int ni = 0; ni < 8; ni++) {
        __half2 h = __floats2half2_rn(cc[mi][ni][rr * 2 + 0], cc[mi][ni][rr * 2 + 1]);
        *(__half2*)(prow + wn + ni * 8 + 2 * tq) = h;
      }
    }
  }
}

// ---------------- gather: out[t] = sum_j w_j * (parth[slot_j] + b2[e_j]) ----------------
__global__ __launch_bounds__(256) void gather_kernel(const float* __restrict__ b2,
                                                     float* __restrict__ out) {
  int t = blockIdx.y;
  int h = blockIdx.x * 1024 + threadIdx.x * 4;
  float4 acc = {0.f, 0.f, 0.f, 0.f};
#pragma unroll
  for (int j = 0; j < TOPK; j++) {
    int sidx = g_tslot[t * TOPK + j];
    float wj = g_twt[t * TOPK + j];
    int e = sidx >> 12;
    uint2 praw = *(const uint2*)(g_parth + (size_t)sidx * 2048 + h);
    __half2 p01 = *(__half2*)&praw.x;
    __half2 p23 = *(__half2*)&praw.y;
    float2 f01 = __half22float2(p01);
    float2 f23 = __half22float2(p23);
    float4 b = *(const float4*)(b2 + (size_t)e * 2048 + h);
    acc.x += wj * (f01.x + b.x);
    acc.y += wj * (f01.y + b.y);
    acc.z += wj * (f23.x + b.z);
    acc.w += wj * (f23.y + b.w);
  }
  *(float4*)(out + (size_t)t * 2048 + h) = acc;
}

// ---------------- launch ----------------
extern "C" void kernel_launch(void* const* d_in, const int* in_sizes, int n_in,
                              void* d_out, int out_size) {
  (void)in_sizes; (void)n_in; (void)out_size;
  const float* hs = (const float*)d_in[0];
  const float* rw = (const float*)d_in[1];
  const float* rb = (const float*)d_in[2];
  const float* w1 = (const float*)d_in[3];
  const float* b1 = (const float*)d_in[4];
  const float* w2 = (const float*)d_in[5];
  const float* b2 = (const float*)d_in[6];
  float* out = (float*)d_out;

  // one-time host-side stream/event setup (outside graph capture on first call)
  static cudaStream_t s_w = nullptr;
  static cudaEvent_t ev_fork = nullptr, ev_w1 = nullptr, ev_w2 = nullptr;
  if (s_w == nullptr) {
    cudaStreamCreateWithFlags(&s_w, cudaStreamNonBlocking);
    cudaEventCreateWithFlags(&ev_fork, cudaEventDisableTiming);
    cudaEventCreateWithFlags(&ev_w1, cudaEventDisableTiming);
    cudaEventCreateWithFlags(&ev_w2, cudaEventDisableTiming);
  }

  void *pxh, *pw1h, *pw2h, *pcnt;
  cudaGetSymbolAddress(&pxh, g_xh);
  cudaGetSymbolAddress(&pw1h, g_w1h);
  cudaGetSymbolAddress(&pw2h, g_w2h);
  cudaGetSymbolAddress(&pcnt, g_cnt);

  cudaFuncSetAttribute(gemm1_kernel, cudaFuncAttributeMaxDynamicSharedMemorySize, SMEM1);
  cudaFuncSetAttribute(gemm2_kernel, cudaFuncAttributeMaxDynamicSharedMemorySize, SMEM2);

  cudaMemsetAsync(pcnt, 0, NEXP * sizeof(int));
  cudaEventRecord(ev_fork, 0);

  // single side stream: w1 conversion FIRST (full HBM bandwidth -> earliest
  // gemm1 start), then w2 conversion (hides under gemm1).
  cudaStreamWaitEvent(s_w, ev_fork, 0);
  cvt_kernel<<<(int)(((size_t)NEXP * HDIM * 4096) / 1024), 256, 0, s_w>>>(w1, (__half*)pw1h);
  cudaEventRecord(ev_w1, s_w);
  cvt_kernel<<<(int)(((size_t)NEXP * IDIM * HDIM) / 1024), 256, 0, s_w>>>(w2, (__half*)pw2h);
  cudaEventRecord(ev_w2, s_w);

  // main stream: router + X conversion overlap with weight conversions
  router_kernel<<<TMAX / 8, 256>>>(hs, rw, rb);
  cvt_kernel<<<(int)(((size_t)TMAX * HDIM) / 1024), 256>>>(hs, (__half*)pxh);

  cudaStreamWaitEvent(0, ev_w1, 0);
  dim3 g1(TMAX / 128, 32, NEXP);
  gemm1_kernel<<<g1, 256, SMEM1>>>(b1);

  cudaStreamWaitEvent(0, ev_w2, 0);
  dim3 g2(TMAX / 128, 16, NEXP);
  gemm2_kernel<<<g2, 256, SMEM2>>>();

  dim3 gg(2, TMAX);
  gather_kernel<<<gg, 256>>>(b2, out);
}

// round 16
// speedup vs baseline: 1.0349x; 1.0349x over previous
#include <cuda_runtime.h>
#include <cuda_fp16.h>
#include <cstdint>
#include <math.h>

#define NEXP 16
#define TOPK 4
#define HDIM 2048
#define IDIM 2048
#define TMAX 4096
#define ALPHA 1.702f
#define LIMIT 7.0f
#define NKB 32     // 2048 / 64
#define KHALF 64   // k-halfs per stage
#define LDK 144    // A row pitch bytes

__device__ int    g_cnt[NEXP];
__device__ int    g_tok[NEXP * TMAX];
__device__ int    g_tslot[TMAX * TOPK];
__device__ float  g_twt[TMAX * TOPK];
__device__ __half g_xh[(size_t)TMAX * HDIM];
__device__ __half g_w1h[(size_t)NEXP * HDIM * 4096];   // fp16 w1, native [k][n]
__device__ __half g_w2h[(size_t)NEXP * IDIM * HDIM];   // fp16 w2, native [k][n]
__device__ __half g_acth[(size_t)NEXP * TMAX * IDIM];
__device__ __half g_parth[(size_t)NEXP * TMAX * HDIM]; // fp16 partials

// ---------------- helpers ----------------
__device__ __forceinline__ void cp16(const void* smem_dst, const void* gsrc, bool pred) {
  uint32_t d = (uint32_t)__cvta_generic_to_shared(smem_dst);
  int sz = pred ? 16 : 0;
  asm volatile("cp.async.cg.shared.global [%0], [%1], 16, %2;" :: "r"(d), "l"(gsrc), "r"(sz));
}
__device__ __forceinline__ void cp_commit() { asm volatile("cp.async.commit_group;"); }

__device__ __forceinline__ void mma16(float* c, const uint32_t* a, const uint32_t* b) {
  asm volatile(
      "mma.sync.aligned.m16n8k16.row.col.f32.f16.f16.f32 "
      "{%0,%1,%2,%3}, {%4,%5,%6,%7}, {%8,%9}, {%0,%1,%2,%3};"
      : "+f"(c[0]), "+f"(c[1]), "+f"(c[2]), "+f"(c[3])
      : "r"(a[0]), "r"(a[1]), "r"(a[2]), "r"(a[3]), "r"(b[0]), "r"(b[1]));
}
__device__ __forceinline__ uint32_t lds32(const char* smem, uint32_t off) {
  return *(const uint32_t*)(smem + off);
}
__device__ __forceinline__ void ldmx4t(uint32_t& r0, uint32_t& r1, uint32_t& r2, uint32_t& r3,
                                       uint32_t addr) {
  asm volatile("ldmatrix.sync.aligned.m8n8.x4.trans.shared.b16 {%0,%1,%2,%3}, [%4];"
               : "=r"(r0), "=r"(r1), "=r"(r2), "=r"(r3) : "r"(addr));
}

// ---------------- router (fused X fp16 conversion) ----------------
__global__ __launch_bounds__(256) void router_kernel(const float* __restrict__ x,
                                                     const float* __restrict__ rw,
                                                     const float* __restrict__ rb) {
  int warp = threadIdx.x >> 5, lane = threadIdx.x & 31;
  int t = blockIdx.x * 8 + warp;
  float acc[NEXP];
#pragma unroll
  for (int e = 0; e < NEXP; e++) acc[e] = 0.f;
  const float* xr = x + (size_t)t * HDIM;
  __half* xhr = g_xh + (size_t)t * HDIM;
  for (int h = lane; h < HDIM; h += 32) {
    float xv = xr[h];
    xhr[h] = __float2half_rn(xv);
#pragma unroll
    for (int e = 0; e < NEXP; e++) acc[e] = fmaf(xv, rw[e * HDIM + h], acc[e]);
  }
#pragma unroll
  for (int e = 0; e < NEXP; e++)
#pragma unroll
    for (int o = 16; o > 0; o >>= 1) acc[e] += __shfl_xor_sync(0xffffffffu, acc[e], o);
  if (lane == 0) {
    float v[NEXP];
#pragma unroll
    for (int e = 0; e < NEXP; e++) v[e] = acc[e] + rb[e];
    int ids[TOPK]; float vals[TOPK];
#pragma unroll
    for (int j = 0; j < TOPK; j++) {
      float best = -1e30f; int bi = 0;
#pragma unroll
      for (int e = 0; e < NEXP; e++)
        if (v[e] > best) { best = v[e]; bi = e; }
      ids[j] = bi; vals[j] = best; v[bi] = -1e30f;
    }
    float m = vals[0], s = 0.f, w[TOPK];
#pragma unroll
    for (int j = 0; j < TOPK; j++) { w[j] = expf(vals[j] - m); s += w[j]; }
    float inv = 1.f / s;
#pragma unroll
    for (int j = 0; j < TOPK; j++) {
      int e = ids[j];
      int p = atomicAdd(&g_cnt[e], 1);
      g_tok[e * TMAX + p] = t;
      g_tslot[t * TOPK + j] = e * TMAX + p;
      g_twt[t * TOPK + j] = w[j] * inv;
    }
  }
}

// ---------------- prep: fp16 conversions ----------------
__global__ __launch_bounds__(256) void cvt_kernel(const float* __restrict__ src,
                                                  __half* __restrict__ dst) {
  size_t i = ((size_t)blockIdx.x * 256 + threadIdx.x);
  float4 v = ((const float4*)src)[i];
  __half2 h0 = __floats2half2_rn(v.x, v.y);
  __half2 h1 = __floats2half2_rn(v.z, v.w);
  uint2 o = { *(uint32_t*)&h0, *(uint32_t*)&h1 };
  ((uint2*)dst)[i] = o;
}

// ---------------- GEMM1: X @ w1 (gate|up) -> clipped GLU -> g_acth ----------------
// CTA tile: 128m x (64 gate + 64 up). 256 threads, 2 CTAs/SM.
// stage s at s*34816: A [128 x LDK] at +0, B [64 k-rows x 256B] at +18432
// per k-row: chunks j=0..7 gate cols n0+j*8, j=8..15 up cols 2048+n0+(j-8)*8
#define STG1 34816
#define SMEM1 (2 * STG1 + 512)

__global__ __launch_bounds__(256, 2) void gemm1_kernel(const float* __restrict__ b1) {
  int e = blockIdx.z;
  int cnt = g_cnt[e];
  int m0 = blockIdx.x * 128;
  if (m0 >= cnt) return;
  int n0 = blockIdx.y * 64;

  extern __shared__ __align__(16) char smem[];
  uint32_t sbase = (uint32_t)__cvta_generic_to_shared(smem);
  int* toks = (int*)(smem + 2 * STG1);
  int tid = threadIdx.x, w = tid >> 5, lane = tid & 31;
  int g = lane >> 2, tq = lane & 3;

  if (tid < 128) toks[tid] = (m0 + tid < cnt) ? g_tok[e * TMAX + m0 + tid] : -1;
  __syncthreads();

  // A: 1024 chunks, 4 per thread
  const __half* asrc[4]; uint32_t adst[4]; bool apred[4];
#pragma unroll
  for (int q = 0; q < 4; q++) {
    int idx = tid + q * 256;
    int row = idx >> 3, ch = idx & 7;
    int tok = toks[row];
    apred[q] = tok >= 0;
    asrc[q] = g_xh + (size_t)(tok < 0 ? 0 : tok) * HDIM + ch * 8;
    adst[q] = row * LDK + ch * 16;
  }

  // B: 1024 chunks (64 rows x 16), 4 per thread
  const __half* w1e = g_w1h + (size_t)e * HDIM * 4096;
  const __half* bsrc[4]; uint32_t bdst[4];
#pragma unroll
  for (int q = 0; q < 4; q++) {
    int C = tid + q * 256;
    int k = C >> 4, j = C & 15;
    int col = (j < 8) ? (n0 + j * 8) : (2048 + n0 + (j - 8) * 8);
    bsrc[q] = w1e + (size_t)k * 4096 + col;
    bdst[q] = 18432 + k * 256 + ((j ^ (k & 7)) << 4);
  }

  auto ld = [&](int kb) {
    char* base = smem + (kb & 1) * STG1;
    size_t ako = (size_t)kb * KHALF;
#pragma unroll
    for (int q = 0; q < 4; q++) cp16(base + adst[q], asrc[q] + ako, apred[q]);
    size_t bko = (size_t)kb * KHALF * 4096;
#pragma unroll
    for (int q = 0; q < 4; q++) cp16(base + bdst[q], bsrc[q] + bko, true);
    cp_commit();
  };

  float cg[2][4][4], cu[2][4][4];
#pragma unroll
  for (int mi = 0; mi < 2; mi++)
#pragma unroll
    for (int ni = 0; ni < 4; ni++)
#pragma unroll
      for (int q = 0; q < 4; q++) { cg[mi][ni][q] = 0.f; cu[mi][ni][q] = 0.f; }

  int wm = (w & 3) * 32, wn = (w >> 2) * 32;   // 4 m-groups x 2 n-groups
  int lr = lane & 7, lci = lane >> 4;
  uint32_t krow = ((lane >> 3) & 1) * 8 + lr;
  uint32_t k7 = krow & 7;
  uint32_t browoff = krow * 256;
  uint32_t cgb = wn >> 3;          // gate chunks cgb..cgb+3
  uint32_t cub = 8 + (wn >> 3);    // up chunks

  ld(0);

  for (int kb = 0; kb < NKB; kb++) {
    asm volatile("cp.async.wait_group 0;");
    __syncthreads();
    if (kb + 1 < NKB) ld(kb + 1);
    const char* Ab = smem + (kb & 1) * STG1;
    uint32_t Bu = sbase + (kb & 1) * STG1 + 18432;
#pragma unroll
    for (int kk = 0; kk < 4; kk++) {
      uint32_t a[2][4];
#pragma unroll
      for (int mi = 0; mi < 2; mi++) {
        uint32_t base = (wm + mi * 16 + g) * LDK + kk * 32 + tq * 4;
        a[mi][0] = lds32(Ab, base);
        a[mi][1] = lds32(Ab, base + 8 * LDK);
        a[mi][2] = lds32(Ab, base + 16);
        a[mi][3] = lds32(Ab, base + 8 * LDK + 16);
      }
      uint32_t bg[4][2], bu[4][2];
      uint32_t kkoff = Bu + kk * 4096 + browoff;
#pragma unroll
      for (int p = 0; p < 2; p++) {
        uint32_t c0 = cgb + 2 * p + lci;
        ldmx4t(bg[2 * p][0], bg[2 * p][1], bg[2 * p + 1][0], bg[2 * p + 1][1],
               kkoff + ((c0 ^ k7) << 4));
        uint32_t c1 = cub + 2 * p + lci;
        ldmx4t(bu[2 * p][0], bu[2 * p][1], bu[2 * p + 1][0], bu[2 * p + 1][1],
               kkoff + ((c1 ^ k7) << 4));
      }
#pragma unroll
      for (int ni = 0; ni < 4; ni++)
#pragma unroll
        for (int mi = 0; mi < 2; mi++) {
          mma16(cg[mi][ni], a[mi], bg[ni]);
          mma16(cu[mi][ni], a[mi], bu[ni]);
        }
    }
  }

  const float* b1e = b1 + (size_t)e * 4096;
#pragma unroll
  for (int ni = 0; ni < 4; ni++) {
    int col = n0 + wn + ni * 8 + 2 * tq;
    float bg0 = b1e[col], bg1 = b1e[col + 1];
    float bu0 = b1e[2048 + col], bu1 = b1e[2048 + col + 1];
#pragma unroll
    for (int mi = 0; mi < 2; mi++) {
#pragma unroll
      for (int rr = 0; rr < 2; rr++) {
        int rl = wm + mi * 16 + rr * 8 + g;
        if (m0 + rl >= cnt) continue;
        float gv0 = cg[mi][ni][rr * 2 + 0] + bg0;
        float gv1 = cg[mi][ni][rr * 2 + 1] + bg1;
        float uv0 = cu[mi][ni][rr * 2 + 0] + bu0;
        float uv1 = cu[mi][ni][rr * 2 + 1] + bu1;
        gv0 = fminf(gv0, LIMIT); gv1 = fminf(gv1, LIMIT);
        uv0 = fminf(fmaxf(uv0, -LIMIT), LIMIT);
        uv1 = fminf(fmaxf(uv1, -LIMIT), LIMIT);
        float a0 = (uv0 + 1.f) * gv0 / (1.f + __expf(-ALPHA * gv0));
        float a1 = (uv1 + 1.f) * gv1 / (1.f + __expf(-ALPHA * gv1));
        __half2 h = __floats2half2_rn(a0, a1);
        *(__half2*)(g_acth + ((size_t)e * TMAX + m0 + rl) * 2048 + col) = h;
      }
    }
  }
}

// ---------------- GEMM2: acts @ w2 -> g_parth (fp16 partials) ----------------
// stage s at s*34816: A [128 x LDK] at +0, B [64 k-rows x 256B] at +18432
#define STG2 34816
#define SMEM2 (2 * STG2)

__global__ __launch_bounds__(256, 2) void gemm2_kernel() {
  int e = blockIdx.z;
  int cnt = g_cnt[e];
  int m0 = blockIdx.x * 128;
  if (m0 >= cnt) return;
  int n0 = blockIdx.y * 128;

  extern __shared__ __align__(16) char smem[];
  uint32_t sbase = (uint32_t)__cvta_generic_to_shared(smem);
  int tid = threadIdx.x, w = tid >> 5, lane = tid & 31;
  int g = lane >> 2, tq = lane & 3;

  const __half* acte = g_acth + (size_t)e * TMAX * 2048;
  const __half* w2h = g_w2h + (size_t)e * IDIM * HDIM;

  // A: 1024 chunks, 4 per thread
  const __half* asrc[4]; uint32_t adst[4]; bool apred[4];
#pragma unroll
  for (int q = 0; q < 4; q++) {
    int idx = tid + q * 256;
    int row = idx >> 3, ch = idx & 7;
    apred[q] = (m0 + row) < cnt;
    asrc[q] = acte + (size_t)(m0 + row) * 2048 + ch * 8;
    adst[q] = row * LDK + ch * 16;
  }
  // B: 1024 chunks, 4 per thread
  const __half* bsrc[4]; uint32_t bdst[4];
#pragma unroll
  for (int q = 0; q < 4; q++) {
    int C = tid + q * 256;
    int k = C >> 4, j = C & 15;
    bsrc[q] = w2h + (size_t)k * 2048 + n0 + j * 8;
    bdst[q] = 18432 + k * 256 + ((j ^ (k & 7)) << 4);
  }

  auto ld = [&](int kb) {
    char* base = smem + (kb & 1) * STG2;
    size_t ako = (size_t)kb * KHALF;
#pragma unroll
    for (int q = 0; q < 4; q++) cp16(base + adst[q], asrc[q] + ako, apred[q]);
    size_t bko = (size_t)kb * KHALF * 2048;
#pragma unroll
    for (int q = 0; q < 4; q++) cp16(base + bdst[q], bsrc[q] + bko, true);
    cp_commit();
  };

  float cc[2][8][4];
#pragma unroll
  for (int mi = 0; mi < 2; mi++)
#pragma unroll
    for (int ni = 0; ni < 8; ni++)
#pragma unroll
      for (int q = 0; q < 4; q++) cc[mi][ni][q] = 0.f;

  int wm = (w & 3) * 32, wn = (w >> 2) * 64;
  int lr = lane & 7, lci = lane >> 4;
  uint32_t krow = ((lane >> 3) & 1) * 8 + lr;
  uint32_t k7 = krow & 7;
  uint32_t browoff = krow * 256;
  uint32_t cb = wn >> 3;

  ld(0);

  for (int kb = 0; kb < NKB; kb++) {
    asm volatile("cp.async.wait_group 0;");
    __syncthreads();
    if (kb + 1 < NKB) ld(kb + 1);
    const char* Ab = smem + (kb & 1) * STG2;
    uint32_t Bu = sbase + (kb & 1) * STG2 + 18432;
#pragma unroll
    for (int kk = 0; kk < 4; kk++) {
      uint32_t a[2][4];
#pragma unroll
      for (int mi = 0; mi < 2; mi++) {
        uint32_t base = (wm + mi * 16 + g) * LDK + kk * 32 + tq * 4;
        a[mi][0] = lds32(Ab, base);
        a[mi][1] = lds32(Ab, base + 8 * LDK);
        a[mi][2] = lds32(Ab, base + 16);
        a[mi][3] = lds32(Ab, base + 8 * LDK + 16);
      }
      uint32_t b[8][2];
      uint32_t kkoff = Bu + kk * 4096 + browoff;
#pragma unroll
      for (int p = 0; p < 4; p++) {
        uint32_t c0 = cb + 2 * p + lci;
        ldmx4t(b[2 * p][0], b[2 * p][1], b[2 * p + 1][0], b[2 * p + 1][1],
               kkoff + ((c0 ^ k7) << 4));
      }
#pragma unroll
      for (int ni = 0; ni < 8; ni++)
#pragma unroll
        for (int mi = 0; mi < 2; mi++) mma16(cc[mi][ni], a[mi], b[ni]);
    }
  }

  __half* parte = g_parth + (size_t)e * TMAX * 2048;
#pragma unroll
  for (int mi = 0; mi < 2; mi++) {
#pragma unroll
    for (int rr = 0; rr < 2; rr++) {
      int rl = wm + mi * 16 + rr * 8 + g;
      if (m0 + rl >= cnt) continue;
      __half* prow = parte + (size_t)(m0 + rl) * 2048 + n0;
#pragma unroll
      for (int ni = 0; ni < 8; ni++) {
        __half2 h = __floats2half2_rn(cc[mi][ni][rr * 2 + 0], cc[mi][ni][rr * 2 + 1]);
        *(__half2*)(prow + wn + ni * 8 + 2 * tq) = h;
      }
    }
  }
}

// ---------------- gather: out[t] = sum_j w_j * (parth[slot_j] + b2[e_j]) ----------------
__global__ __launch_bounds__(256) void gather_kernel(const float* __restrict__ b2,
                                                     float* __restrict__ out) {
  int t = blockIdx.y;
  int h = blockIdx.x * 1024 + threadIdx.x * 4;
  float4 acc = {0.f, 0.f, 0.f, 0.f};
#pragma unroll
  for (int j = 0; j < TOPK; j++) {
    int sidx = g_tslot[t * TOPK + j];
    float wj = g_twt[t * TOPK + j];
    int e = sidx >> 12;
    uint2 praw = *(const uint2*)(g_parth + (size_t)sidx * 2048 + h);
    __half2 p01 = *(__half2*)&praw.x;
    __half2 p23 = *(__half2*)&praw.y;
    float2 f01 = __half22float2(p01);
    float2 f23 = __half22float2(p23);
    float4 b = *(const float4*)(b2 + (size_t)e * 2048 + h);
    acc.x += wj * (f01.x + b.x);
    acc.y += wj * (f01.y + b.y);
    acc.z += wj * (f23.x + b.z);
    acc.w += wj * (f23.y + b.w);
  }
  *(float4*)(out + (size_t)t * 2048 + h) = acc;
}

// ---------------- launch ----------------
extern "C" void kernel_launch(void* const* d_in, const int* in_sizes, int n_in,
                              void* d_out, int out_size) {
  (void)in_sizes; (void)n_in; (void)out_size;
  const float* hs = (const float*)d_in[0];
  const float* rw = (const float*)d_in[1];
  const float* rb = (const float*)d_in[2];
  const float* w1 = (const float*)d_in[3];
  const float* b1 = (const float*)d_in[4];
  const float* w2 = (const float*)d_in[5];
  const float* b2 = (const float*)d_in[6];
  float* out = (float*)d_out;

  // one-time host-side stream/event setup (outside graph capture on first call)
  static cudaStream_t s_w1 = nullptr, s_w2 = nullptr;
  static cudaEvent_t ev_fork = nullptr, ev_w1 = nullptr, ev_w2 = nullptr;
  if (s_w1 == nullptr) {
    cudaStreamCreateWithFlags(&s_w1, cudaStreamNonBlocking);
    cudaStreamCreateWithFlags(&s_w2, cudaStreamNonBlocking);
    cudaEventCreateWithFlags(&ev_fork, cudaEventDisableTiming);
    cudaEventCreateWithFlags(&ev_w1, cudaEventDisableTiming);
    cudaEventCreateWithFlags(&ev_w2, cudaEventDisableTiming);
  }

  void *pw1h, *pw2h, *pcnt;
  cudaGetSymbolAddress(&pw1h, g_w1h);
  cudaGetSymbolAddress(&pw2h, g_w2h);
  cudaGetSymbolAddress(&pcnt, g_cnt);

  cudaFuncSetAttribute(gemm1_kernel, cudaFuncAttributeMaxDynamicSharedMemorySize, SMEM1);
  cudaFuncSetAttribute(gemm2_kernel, cudaFuncAttributeMaxDynamicSharedMemorySize, SMEM2);

  cudaMemsetAsync(pcnt, 0, NEXP * sizeof(int));
  cudaEventRecord(ev_fork, 0);

  // side stream 1: w1 conversion FIRST in enqueue order (gates gemm1)
  cudaStreamWaitEvent(s_w1, ev_fork, 0);
  cvt_kernel<<<(int)(((size_t)NEXP * HDIM * 4096) / 1024), 256, 0, s_w1>>>(w1, (__half*)pw1h);
  cudaEventRecord(ev_w1, s_w1);

  // side stream 2: w2 conversion (needed only by gemm2; hides under gemm1)
  cudaStreamWaitEvent(s_w2, ev_fork, 0);
  cvt_kernel<<<(int)(((size_t)NEXP * IDIM * HDIM) / 1024), 256, 0, s_w2>>>(w2, (__half*)pw2h);
  cudaEventRecord(ev_w2, s_w2);

  // main stream: router (with fused X fp16 conversion)
  router_kernel<<<TMAX / 8, 256>>>(hs, rw, rb);

  cudaStreamWaitEvent(0, ev_w1, 0);
  dim3 g1(TMAX / 128, 32, NEXP);
  gemm1_kernel<<<g1, 256, SMEM1>>>(b1);

  cudaStreamWaitEvent(0, ev_w2, 0);
  dim3 g2(TMAX / 128, 16, NEXP);
  gemm2_kernel<<<g2, 256, SMEM2>>>();

  dim3 gg(2, TMAX);
  gather_kernel<<<gg, 256>>>(b2, out);
}

// round 17
// speedup vs baseline: 1.0788x; 1.0424x over previous
#include <cuda_runtime.h>
#include <cuda_fp16.h>
#include <cstdint>
#include <math.h>

#define NEXP 16
#define TOPK 4
#define HDIM 2048
#define IDIM 2048
#define TMAX 4096
#define ALPHA 1.702f
#define LIMIT 7.0f
#define NKB 32     // 2048 / 64
#define KHALF 64   // k-halfs per stage
#define LDK 144    // A row pitch bytes

__device__ int    g_cnt[NEXP];
__device__ int    g_tok[NEXP * TMAX];
__device__ int    g_tslot[TMAX * TOPK];
__device__ float  g_twt[TMAX * TOPK];
__device__ __half g_xh[(size_t)TMAX * HDIM];
__device__ __half g_w1h[(size_t)NEXP * HDIM * 4096];   // fp16 w1, native [k][n]
__device__ __half g_w2h[(size_t)NEXP * IDIM * HDIM];   // fp16 w2, native [k][n]
__device__ __half g_acth[(size_t)NEXP * TMAX * IDIM];
__device__ __half g_parth[(size_t)NEXP * TMAX * HDIM]; // fp16 partials

// ---------------- helpers ----------------
__device__ __forceinline__ void cp16(const void* smem_dst, const void* gsrc, bool pred) {
  uint32_t d = (uint32_t)__cvta_generic_to_shared(smem_dst);
  int sz = pred ? 16 : 0;
  asm volatile("cp.async.cg.shared.global [%0], [%1], 16, %2;" :: "r"(d), "l"(gsrc), "r"(sz));
}
__device__ __forceinline__ void cp_commit() { asm volatile("cp.async.commit_group;"); }

__device__ __forceinline__ void mma16(float* c, const uint32_t* a, const uint32_t* b) {
  asm volatile(
      "mma.sync.aligned.m16n8k16.row.col.f32.f16.f16.f32 "
      "{%0,%1,%2,%3}, {%4,%5,%6,%7}, {%8,%9}, {%0,%1,%2,%3};"
      : "+f"(c[0]), "+f"(c[1]), "+f"(c[2]), "+f"(c[3])
      : "r"(a[0]), "r"(a[1]), "r"(a[2]), "r"(a[3]), "r"(b[0]), "r"(b[1]));
}
__device__ __forceinline__ void ldmx4(uint32_t& r0, uint32_t& r1, uint32_t& r2, uint32_t& r3,
                                      uint32_t addr) {
  asm volatile("ldmatrix.sync.aligned.m8n8.x4.shared.b16 {%0,%1,%2,%3}, [%4];"
               : "=r"(r0), "=r"(r1), "=r"(r2), "=r"(r3) : "r"(addr));
}
__device__ __forceinline__ void ldmx4t(uint32_t& r0, uint32_t& r1, uint32_t& r2, uint32_t& r3,
                                       uint32_t addr) {
  asm volatile("ldmatrix.sync.aligned.m8n8.x4.trans.shared.b16 {%0,%1,%2,%3}, [%4];"
               : "=r"(r0), "=r"(r1), "=r"(r2), "=r"(r3) : "r"(addr));
}

// ---------------- router (fused X fp16 conversion) ----------------
__global__ __launch_bounds__(256) void router_kernel(const float* __restrict__ x,
                                                     const float* __restrict__ rw,
                                                     const float* __restrict__ rb) {
  int warp = threadIdx.x >> 5, lane = threadIdx.x & 31;
  int t = blockIdx.x * 8 + warp;
  float acc[NEXP];
#pragma unroll
  for (int e = 0; e < NEXP; e++) acc[e] = 0.f;
  const float* xr = x + (size_t)t * HDIM;
  __half* xhr = g_xh + (size_t)t * HDIM;
  for (int h = lane; h < HDIM; h += 32) {
    float xv = xr[h];
    xhr[h] = __float2half_rn(xv);
#pragma unroll
    for (int e = 0; e < NEXP; e++) acc[e] = fmaf(xv, rw[e * HDIM + h], acc[e]);
  }
#pragma unroll
  for (int e = 0; e < NEXP; e++)
#pragma unroll
    for (int o = 16; o > 0; o >>= 1) acc[e] += __shfl_xor_sync(0xffffffffu, acc[e], o);
  if (lane == 0) {
    float v[NEXP];
#pragma unroll
    for (int e = 0; e < NEXP; e++) v[e] = acc[e] + rb[e];
    int ids[TOPK]; float vals[TOPK];
#pragma unroll
    for (int j = 0; j < TOPK; j++) {
      float best = -1e30f; int bi = 0;
#pragma unroll
      for (int e = 0; e < NEXP; e++)
        if (v[e] > best) { best = v[e]; bi = e; }
      ids[j] = bi; vals[j] = best; v[bi] = -1e30f;
    }
    float m = vals[0], s = 0.f, w[TOPK];
#pragma unroll
    for (int j = 0; j < TOPK; j++) { w[j] = expf(vals[j] - m); s += w[j]; }
    float inv = 1.f / s;
#pragma unroll
    for (int j = 0; j < TOPK; j++) {
      int e = ids[j];
      int p = atomicAdd(&g_cnt[e], 1);
      g_tok[e * TMAX + p] = t;
      g_tslot[t * TOPK + j] = e * TMAX + p;
      g_twt[t * TOPK + j] = w[j] * inv;
    }
  }
}

// ---------------- prep: fp16 conversions ----------------
__global__ __launch_bounds__(256) void cvt_kernel(const float* __restrict__ src,
                                                  __half* __restrict__ dst) {
  size_t i = ((size_t)blockIdx.x * 256 + threadIdx.x);
  float4 v = ((const float4*)src)[i];
  __half2 h0 = __floats2half2_rn(v.x, v.y);
  __half2 h1 = __floats2half2_rn(v.z, v.w);
  uint2 o = { *(uint32_t*)&h0, *(uint32_t*)&h1 };
  ((uint2*)dst)[i] = o;
}

// ---------------- GEMM1: X @ w1 (gate|up) -> clipped GLU -> g_acth ----------------
// CTA tile: 128m x (64 gate + 64 up). 256 threads, 2 CTAs/SM.
// stage s at s*34816: A [128 x LDK] at +0, B [64 k-rows x 256B] at +18432
#define STG1 34816
#define SMEM1 (2 * STG1 + 512)

__global__ __launch_bounds__(256, 2) void gemm1_kernel(const float* __restrict__ b1) {
  int e = blockIdx.z;
  int cnt = g_cnt[e];
  int m0 = blockIdx.x * 128;
  if (m0 >= cnt) return;
  int n0 = blockIdx.y * 64;

  extern __shared__ __align__(16) char smem[];
  uint32_t sbase = (uint32_t)__cvta_generic_to_shared(smem);
  int* toks = (int*)(smem + 2 * STG1);
  int tid = threadIdx.x, w = tid >> 5, lane = tid & 31;
  int g = lane >> 2, tq = lane & 3;

  if (tid < 128) toks[tid] = (m0 + tid < cnt) ? g_tok[e * TMAX + m0 + tid] : -1;
  __syncthreads();

  // A: 1024 chunks, 4 per thread
  const __half* asrc[4]; uint32_t adst[4]; bool apred[4];
#pragma unroll
  for (int q = 0; q < 4; q++) {
    int idx = tid + q * 256;
    int row = idx >> 3, ch = idx & 7;
    int tok = toks[row];
    apred[q] = tok >= 0;
    asrc[q] = g_xh + (size_t)(tok < 0 ? 0 : tok) * HDIM + ch * 8;
    adst[q] = row * LDK + ch * 16;
  }

  // B: 1024 chunks (64 rows x 16), 4 per thread
  const __half* w1e = g_w1h + (size_t)e * HDIM * 4096;
  const __half* bsrc[4]; uint32_t bdst[4];
#pragma unroll
  for (int q = 0; q < 4; q++) {
    int C = tid + q * 256;
    int k = C >> 4, j = C & 15;
    int col = (j < 8) ? (n0 + j * 8) : (2048 + n0 + (j - 8) * 8);
    bsrc[q] = w1e + (size_t)k * 4096 + col;
    bdst[q] = 18432 + k * 256 + ((j ^ (k & 7)) << 4);
  }

  auto ld = [&](int kb) {
    char* base = smem + (kb & 1) * STG1;
    size_t ako = (size_t)kb * KHALF;
#pragma unroll
    for (int q = 0; q < 4; q++) cp16(base + adst[q], asrc[q] + ako, apred[q]);
    size_t bko = (size_t)kb * KHALF * 4096;
#pragma unroll
    for (int q = 0; q < 4; q++) cp16(base + bdst[q], bsrc[q] + bko, true);
    cp_commit();
  };

  float cg[2][4][4], cu[2][4][4];
#pragma unroll
  for (int mi = 0; mi < 2; mi++)
#pragma unroll
    for (int ni = 0; ni < 4; ni++)
#pragma unroll
      for (int q = 0; q < 4; q++) { cg[mi][ni][q] = 0.f; cu[mi][ni][q] = 0.f; }

  int wm = (w & 3) * 32, wn = (w >> 2) * 32;   // 4 m-groups x 2 n-groups
  int lr = lane & 7, lci = lane >> 4;
  uint32_t krow = ((lane >> 3) & 1) * 8 + lr;
  uint32_t k7 = krow & 7;
  uint32_t browoff = krow * 256;
  uint32_t cgb = wn >> 3;          // gate chunks
  uint32_t cub = 8 + (wn >> 3);    // up chunks
  // ldmatrix A address pieces: lane l -> row (l>>3&1)*8 + (l&7), k-byte (l>>4)*16
  uint32_t aoff = (wm + ((lane >> 3) & 1) * 8 + (lane & 7)) * LDK + ((lane >> 4) << 4);

  ld(0);

  for (int kb = 0; kb < NKB; kb++) {
    asm volatile("cp.async.wait_group 0;");
    __syncthreads();
    if (kb + 1 < NKB) ld(kb + 1);
    uint32_t Au = sbase + (kb & 1) * STG1;
    uint32_t Bu = Au + 18432;
#pragma unroll
    for (int kk = 0; kk < 4; kk++) {
      uint32_t a[2][4];
#pragma unroll
      for (int mi = 0; mi < 2; mi++)
        ldmx4(a[mi][0], a[mi][1], a[mi][2], a[mi][3],
              Au + aoff + mi * 16 * LDK + kk * 32);
      uint32_t bg[4][2], bu[4][2];
      uint32_t kkoff = Bu + kk * 4096 + browoff;
#pragma unroll
      for (int p = 0; p < 2; p++) {
        uint32_t c0 = cgb + 2 * p + lci;
        ldmx4t(bg[2 * p][0], bg[2 * p][1], bg[2 * p + 1][0], bg[2 * p + 1][1],
               kkoff + ((c0 ^ k7) << 4));
        uint32_t c1 = cub + 2 * p + lci;
        ldmx4t(bu[2 * p][0], bu[2 * p][1], bu[2 * p + 1][0], bu[2 * p + 1][1],
               kkoff + ((c1 ^ k7) << 4));
      }
#pragma unroll
      for (int ni = 0; ni < 4; ni++)
#pragma unroll
        for (int mi = 0; mi < 2; mi++) {
          mma16(cg[mi][ni], a[mi], bg[ni]);
          mma16(cu[mi][ni], a[mi], bu[ni]);
        }
    }
  }

  const float* b1e = b1 + (size_t)e * 4096;
#pragma unroll
  for (int ni = 0; ni < 4; ni++) {
    int col = n0 + wn + ni * 8 + 2 * tq;
    float bg0 = b1e[col], bg1 = b1e[col + 1];
    float bu0 = b1e[2048 + col], bu1 = b1e[2048 + col + 1];
#pragma unroll
    for (int mi = 0; mi < 2; mi++) {
#pragma unroll
      for (int rr = 0; rr < 2; rr++) {
        int rl = wm + mi * 16 + rr * 8 + g;
        if (m0 + rl >= cnt) continue;
        float gv0 = cg[mi][ni][rr * 2 + 0] + bg0;
        float gv1 = cg[mi][ni][rr * 2 + 1] + bg1;
        float uv0 = cu[mi][ni][rr * 2 + 0] + bu0;
        float uv1 = cu[mi][ni][rr * 2 + 1] + bu1;
        gv0 = fminf(gv0, LIMIT); gv1 = fminf(gv1, LIMIT);
        uv0 = fminf(fmaxf(uv0, -LIMIT), LIMIT);
        uv1 = fminf(fmaxf(uv1, -LIMIT), LIMIT);
        float a0 = (uv0 + 1.f) * gv0 / (1.f + __expf(-ALPHA * gv0));
        float a1 = (uv1 + 1.f) * gv1 / (1.f + __expf(-ALPHA * gv1));
        __half2 h = __floats2half2_rn(a0, a1);
        *(__half2*)(g_acth + ((size_t)e * TMAX + m0 + rl) * 2048 + col) = h;
      }
    }
  }
}

// ---------------- GEMM2: acts @ w2 -> g_parth (fp16 partials) ----------------
#define STG2 34816
#define SMEM2 (2 * STG2)

__global__ __launch_bounds__(256, 2) void gemm2_kernel() {
  int e = blockIdx.z;
  int cnt = g_cnt[e];
  int m0 = blockIdx.x * 128;
  if (m0 >= cnt) return;
  int n0 = blockIdx.y * 128;

  extern __shared__ __align__(16) char smem[];
  uint32_t sbase = (uint32_t)__cvta_generic_to_shared(smem);
  int tid = threadIdx.x, w = tid >> 5, lane = tid & 31;
  int g = lane >> 2, tq = lane & 3;

  const __half* acte = g_acth + (size_t)e * TMAX * 2048;
  const __half* w2h = g_w2h + (size_t)e * IDIM * HDIM;

  // A: 1024 chunks, 4 per thread
  const __half* asrc[4]; uint32_t adst[4]; bool apred[4];
#pragma unroll
  for (int q = 0; q < 4; q++) {
    int idx = tid + q * 256;
    int row = idx >> 3, ch = idx & 7;
    apred[q] = (m0 + row) < cnt;
    asrc[q] = acte + (size_t)(m0 + row) * 2048 + ch * 8;
    adst[q] = row * LDK + ch * 16;
  }
  // B: 1024 chunks, 4 per thread
  const __half* bsrc[4]; uint32_t bdst[4];
#pragma unroll
  for (int q = 0; q < 4; q++) {
    int C = tid + q * 256;
    int k = C >> 4, j = C & 15;
    bsrc[q] = w2h + (size_t)k * 2048 + n0 + j * 8;
    bdst[q] = 18432 + k * 256 + ((j ^ (k & 7)) << 4);
  }

  auto ld = [&](int kb) {
    char* base = smem + (kb & 1) * STG2;
    size_t ako = (size_t)kb * KHALF;
#pragma unroll
    for (int q = 0; q < 4; q++) cp16(base + adst[q], asrc[q] + ako, apred[q]);
    size_t bko = (size_t)kb * KHALF * 2048;
#pragma unroll
    for (int q = 0; q < 4; q++) cp16(base + bdst[q], bsrc[q] + bko, true);
    cp_commit();
  };

  float cc[2][8][4];
#pragma unroll
  for (int mi = 0; mi < 2; mi++)
#pragma unroll
    for (int ni = 0; ni < 8; ni++)
#pragma unroll
      for (int q = 0; q < 4; q++) cc[mi][ni][q] = 0.f;

  int wm = (w & 3) * 32, wn = (w >> 2) * 64;
  int lr = lane & 7, lci = lane >> 4;
  uint32_t krow = ((lane >> 3) & 1) * 8 + lr;
  uint32_t k7 = krow & 7;
  uint32_t browoff = krow * 256;
  uint32_t cb = wn >> 3;
  uint32_t aoff = (wm + ((lane >> 3) & 1) * 8 + (lane & 7)) * LDK + ((lane >> 4) << 4);

  ld(0);

  for (int kb = 0; kb < NKB; kb++) {
    asm volatile("cp.async.wait_group 0;");
    __syncthreads();
    if (kb + 1 < NKB) ld(kb + 1);
    uint32_t Au = sbase + (kb & 1) * STG2;
    uint32_t Bu = Au + 18432;
#pragma unroll
    for (int kk = 0; kk < 4; kk++) {
      uint32_t a[2][4];
#pragma unroll
      for (int mi = 0; mi < 2; mi++)
        ldmx4(a[mi][0], a[mi][1], a[mi][2], a[mi][3],
              Au + aoff + mi * 16 * LDK + kk * 32);
      uint32_t b[8][2];
      uint32_t kkoff = Bu + kk * 4096 + browoff;
#pragma unroll
      for (int p = 0; p < 4; p++) {
        uint32_t c0 = cb + 2 * p + lci;
        ldmx4t(b[2 * p][0], b[2 * p][1], b[2 * p + 1][0], b[2 * p + 1][1],
               kkoff + ((c0 ^ k7) << 4));
      }
#pragma unroll
      for (int ni = 0; ni < 8; ni++)
#pragma unroll
        for (int mi = 0; mi < 2; mi++) mma16(cc[mi][ni], a[mi], b[ni]);
    }
  }

  __half* parte = g_parth + (size_t)e * TMAX * 2048;
#pragma unroll
  for (int mi = 0; mi < 2; mi++) {
#pragma unroll
    for (int rr = 0; rr < 2; rr++) {
      int rl = wm + mi * 16 + rr * 8 + g;
      if (m0 + rl >= cnt) continue;
      __half* prow = parte + (size_t)(m0 + rl) * 2048 + n0;
#pragma unroll
      for (int ni = 0; ni < 8; ni++) {
        __half2 h = __floats2half2_rn(cc[mi][ni][rr * 2 + 0], cc[mi][ni][rr * 2 + 1]);
        *(__half2*)(prow + wn + ni * 8 + 2 * tq) = h;
      }
    }
  }
}

// ---------------- gather: out[t] = sum_j w_j * (parth[slot_j] + b2[e_j]) ----------------
__global__ __launch_bounds__(256) void gather_kernel(const float* __restrict__ b2,
                                                     float* __restrict__ out) {
  int t = blockIdx.y;
  int h = blockIdx.x * 1024 + threadIdx.x * 4;
  float4 acc = {0.f, 0.f, 0.f, 0.f};
#pragma unroll
  for (int j = 0; j < TOPK; j++) {
    int sidx = g_tslot[t * TOPK + j];
    float wj = g_twt[t * TOPK + j];
    int e = sidx >> 12;
    uint2 praw = *(const uint2*)(g_parth + (size_t)sidx * 2048 + h);
    __half2 p01 = *(__half2*)&praw.x;
    __half2 p23 = *(__half2*)&praw.y;
    float2 f01 = __half22float2(p01);
    float2 f23 = __half22float2(p23);
    float4 b = *(const float4*)(b2 + (size_t)e * 2048 + h);
    acc.x += wj * (f01.x + b.x);
    acc.y += wj * (f01.y + b.y);
    acc.z += wj * (f23.x + b.z);
    acc.w += wj * (f23.y + b.w);
  }
  *(float4*)(out + (size_t)t * 2048 + h) = acc;
}

// ---------------- launch ----------------
extern "C" void kernel_launch(void* const* d_in, const int* in_sizes, int n_in,
                              void* d_out, int out_size) {
  (void)in_sizes; (void)n_in; (void)out_size;
  const float* hs = (const float*)d_in[0];
  const float* rw = (const float*)d_in[1];
  const float* rb = (const float*)d_in[2];
  const float* w1 = (const float*)d_in[3];
  const float* b1 = (const float*)d_in[4];
  const float* w2 = (const float*)d_in[5];
  const float* b2 = (const float*)d_in[6];
  float* out = (float*)d_out;

  // one-time host-side stream/event setup (outside graph capture on first call)
  static cudaStream_t s_w1 = nullptr, s_w2 = nullptr;
  static cudaEvent_t ev_fork = nullptr, ev_w1 = nullptr, ev_w2 = nullptr;
  if (s_w1 == nullptr) {
    cudaStreamCreateWithFlags(&s_w1, cudaStreamNonBlocking);
    cudaStreamCreateWithFlags(&s_w2, cudaStreamNonBlocking);
    cudaEventCreateWithFlags(&ev_fork, cudaEventDisableTiming);
    cudaEventCreateWithFlags(&ev_w1, cudaEventDisableTiming);
    cudaEventCreateWithFlags(&ev_w2, cudaEventDisableTiming);
  }

  void *pw1h, *pw2h, *pcnt;
  cudaGetSymbolAddress(&pw1h, g_w1h);
  cudaGetSymbolAddress(&pw2h, g_w2h);
  cudaGetSymbolAddress(&pcnt, g_cnt);

  cudaFuncSetAttribute(gemm1_kernel, cudaFuncAttributeMaxDynamicSharedMemorySize, SMEM1);
  cudaFuncSetAttribute(gemm2_kernel, cudaFuncAttributeMaxDynamicSharedMemorySize, SMEM2);

  cudaMemsetAsync(pcnt, 0, NEXP * sizeof(int));
  cudaEventRecord(ev_fork, 0);

  // side stream 1: w1 conversion FIRST in enqueue order (gates gemm1)
  cudaStreamWaitEvent(s_w1, ev_fork, 0);
  cvt_kernel<<<(int)(((size_t)NEXP * HDIM * 4096) / 1024), 256, 0, s_w1>>>(w1, (__half*)pw1h);
  cudaEventRecord(ev_w1, s_w1);

  // side stream 2: w2 conversion (needed only by gemm2; hides under gemm1)
  cudaStreamWaitEvent(s_w2, ev_fork, 0);
  cvt_kernel<<<(int)(((size_t)NEXP * IDIM * HDIM) / 1024), 256, 0, s_w2>>>(w2, (__half*)pw2h);
  cudaEventRecord(ev_w2, s_w2);

  // main stream: router (with fused X fp16 conversion)
  router_kernel<<<TMAX / 8, 256>>>(hs, rw, rb);

  cudaStreamWaitEvent(0, ev_w1, 0);
  dim3 g1(TMAX / 128, 32, NEXP);
  gemm1_kernel<<<g1, 256, SMEM1>>>(b1);

  cudaStreamWaitEvent(0, ev_w2, 0);
  dim3 g2(TMAX / 128, 16, NEXP);
  gemm2_kernel<<<g2, 256, SMEM2>>>();

  dim3 gg(2, TMAX);
  gather_kernel<<<gg, 256>>>(b2, out);
}